// round 16
// baseline (speedup 1.0000x reference)
#include <cuda_runtime.h>
#include <cuda.h>
#include <cuda_fp16.h>
#include <cstdint>

// Problem dims
#define TOKENS  32768
#define IN_DIM  8192
#define OUT_DIM 256

// Tiling
#define TILE_M 128
#define KT 64                       // K elements per pipeline stage
#define STAGES 3
#define NS (IN_DIM / KT)            // 128 K-stages (full-K CTA)

// LPT split-K schedule: 148 full-K CTAs + 108 tiles x 4 quarter-K CTAs
#define N_FULL  148
#define N_QTILE (TOKENS / TILE_M - N_FULL)   // 108
#define QSTAGES (NS / 4)                      // 32
#define TILE_ELEMS (TILE_M * OUT_DIM)         // 32768

#define A_STAGE_BYTES (TILE_M * KT * 4)    // 32768 (two 16KB TMA boxes)
#define B_STAGE_BYTES (OUT_DIM * KT * 2)   // 32768 (fp16, slot-permuted)
#define STAGE_TX      (A_STAGE_BYTES + B_STAGE_BYTES)   // 65536

// SMEM layout (all inside the dynamic region; NO static __shared__ anywhere,
// so the extern smem base keeps 16B alignment and mbarriers stay 8B-aligned)
#define SMEM_FULL(s)  ((s) * 16)
#define SMEM_EMPTY(s) ((s) * 16 + 8)
#define SMEM_LAST     512
#define SMEM_A(s)     (1024 + (s) * A_STAGE_BYTES)
#define SMEM_B(s)     (1024 + STAGES * A_STAGE_BYTES + (s) * B_STAGE_BYTES)
#define SMEM_TOTAL    (1024 + STAGES * (A_STAGE_BYTES + B_STAGE_BYTES))   // 197632

// tanh(W) as fp16, K-permuted into MMA slot order, 4 MB device scratch.
__device__ __align__(16) __half g_wt[OUT_DIM * IN_DIM];
// fp32 partials for quarter-K CTAs: [qtile][quarter][128*256]  (56.6 MB)
__device__ __align__(16) float g_part[N_QTILE * 4 * TILE_ELEMS];
// per-split-tile completion counters (self-resetting each launch)
__device__ int g_cnt[N_QTILE];

// ---------------- PTX helpers ----------------
__device__ __forceinline__ uint32_t smem_u32(const void* p) {
    uint32_t a;
    asm("{ .reg .u64 t; cvta.to.shared.u64 t, %1; cvt.u32.u64 %0, t; }" : "=r"(a) : "l"(p));
    return a;
}

#define MBARRIER_INIT(addr, cnt) \
    asm volatile("mbarrier.init.shared.b64 [%0], %1;" :: "r"((uint32_t)(addr)), "r"((uint32_t)(cnt)) : "memory")

#define MBARRIER_ARRIVE(addr) \
    asm volatile("mbarrier.arrive.shared.b64 _, [%0];" :: "r"((uint32_t)(addr)) : "memory")

#define MBARRIER_EXPECT_TX(addr, bytes) \
    asm volatile("mbarrier.arrive.expect_tx.shared.b64 _, [%0], %1;" :: "r"((uint32_t)(addr)), "r"((uint32_t)(bytes)) : "memory")

#define MBARRIER_WAIT_PARITY(mbar_smem_addr, phase_parity) do { \
    uint32_t _mbar = (uint32_t)(mbar_smem_addr); \
    uint32_t _parity = (uint32_t)(phase_parity); \
    uint32_t _done; \
    asm volatile( \
        "{\n\t" \
        ".reg .pred p;\n\t" \
        "mbarrier.try_wait.parity.acquire.cta.shared::cta.b64 p, [%1], %2;\n\t" \
        "selp.b32 %0, 1, 0, p;\n\t" \
        "}" \
        : "=r"(_done) : "r"(_mbar), "r"(_parity) : "memory"); \
    if (!_done) { \
        asm volatile( \
            "{\n\t" \
            ".reg .pred P1;\n\t" \
            "WAIT_LOOP_%=:\n\t" \
            "mbarrier.try_wait.parity.acquire.cta.shared::cta.b64 P1, [%0], %1, 0x989680;\n\t" \
            "@P1 bra.uni WAIT_DONE_%=;\n\t" \
            "bra.uni WAIT_LOOP_%=;\n\t" \
            "WAIT_DONE_%=:\n\t" \
            "}" \
            :: "r"(_mbar), "r"(_parity) : "memory"); \
    } \
} while(0)

#define LDSM_X4(r0, r1, r2, r3, addr) \
    asm volatile("ldmatrix.sync.aligned.m8n8.x4.shared.b16 {%0,%1,%2,%3}, [%4];" \
        : "=r"(r0), "=r"(r1), "=r"(r2), "=r"(r3) : "r"(addr))

// pack two fp32 (given as raw bits) into fp16x2: hi half <- h, lo half <- l
__device__ __forceinline__ uint32_t pack_f16x2(uint32_t h, uint32_t l) {
    uint32_t d;
    asm("cvt.rn.f16x2.f32 %0, %1, %2;" : "=r"(d) : "f"(__uint_as_float(h)), "f"(__uint_as_float(l)));
    return d;
}

__device__ __forceinline__ void mma_f16(float c[4], uint32_t a0, uint32_t a1, uint32_t a2, uint32_t a3,
                                        uint32_t b0, uint32_t b1) {
    asm volatile(
        "mma.sync.aligned.m16n8k16.row.col.f32.f16.f16.f32 "
        "{%0,%1,%2,%3}, {%4,%5,%6,%7}, {%8,%9}, {%0,%1,%2,%3};"
        : "+f"(c[0]), "+f"(c[1]), "+f"(c[2]), "+f"(c[3])
        : "r"(a0), "r"(a1), "r"(a2), "r"(a3), "r"(b0), "r"(b1));
}

// ---------------- Kernels ----------------

// tanh(W) -> fp16 (hardware tanh.approx), written K-permuted into MMA-slot order.
// For phys k position p (0..15) within a 16-chunk:
//   slot = 2*(p&3) + ((p>>2)&1) + (p&8)
__global__ void tanh_prep_kernel(const float* __restrict__ w, __half* __restrict__ wt) {
    int i = blockIdx.x * blockDim.x + threadIdx.x;
    if (i < OUT_DIM * IN_DIM) {
        int n = i / IN_DIM, k = i % IN_DIM;
        int kc = k >> 6, j = k & 63, c = (j >> 4) & 3, p = j & 15;
        int slot = ((p & 3) << 1) + ((p >> 2) & 1) + (p & 8);
        int dst = ((kc * OUT_DIM + n) << 6) + (c << 4) + slot;
        float t;
        asm("tanh.approx.f32 %0, %1;" : "=f"(t) : "f"(w[i]));
        wt[dst] = __float2half_rn(t);
    }
}

__global__ void __launch_bounds__(256, 1) gemm_f16_kernel(
    const __grid_constant__ CUtensorMap tma_a,
    const __grid_constant__ CUtensorMap tma_b,
    float* __restrict__ out)
{
    extern __shared__ char smem[];
    uint32_t sb = smem_u32(smem);
    const int tid = threadIdx.x;
    const int wid = tid >> 5;
    const int lane = tid & 31;
    const int warp_m = wid & 1;        // 2-way M split (64 rows each)
    const int warp_n = wid >> 1;       // 4-way N split (64 cols each)

    // ---- work decode: full-K tile or quarter-K slice ----
    const int bid = blockIdx.x;
    int m_tile, s0, nstage, qt = -1;
    float* obase;
    if (bid < N_FULL) {
        m_tile = bid; s0 = 0; nstage = NS;
        obase = out + (size_t)m_tile * TILE_ELEMS;
    } else {
        const int q = bid - N_FULL;
        qt = q >> 2;
        m_tile = N_FULL + qt;
        s0 = (q & 3) * QSTAGES; nstage = QSTAGES;
        obase = g_part + (size_t)q * TILE_ELEMS;
    }
    const int m0 = m_tile * TILE_M;

    if (tid == 0) {
        #pragma unroll
        for (int s = 0; s < STAGES; s++) {
            MBARRIER_INIT(sb + SMEM_FULL(s), 1);
            MBARRIER_INIT(sb + SMEM_EMPTY(s), 8);   // one arrive per warp
        }
    }
    __syncthreads();

    // prologue: fill all 3 stages
    if (tid == 0) {
        #pragma unroll
        for (int jj = 0; jj < STAGES; jj++) {
            const int j = s0 + jj;
            MBARRIER_EXPECT_TX(sb + SMEM_FULL(jj), STAGE_TX);
            asm volatile(
                "cp.async.bulk.tensor.2d.shared::cta.global.tile.mbarrier::complete_tx::bytes "
                "[%0], [%1, {%2, %3}], [%4];"
                :: "r"(sb + SMEM_A(jj)), "l"(&tma_a),
                   "r"(j * KT), "r"(m0), "r"(sb + SMEM_FULL(jj)) : "memory");
            asm volatile(
                "cp.async.bulk.tensor.2d.shared::cta.global.tile.mbarrier::complete_tx::bytes "
                "[%0], [%1, {%2, %3}], [%4];"
                :: "r"(sb + SMEM_A(jj) + 16384), "l"(&tma_a),
                   "r"(j * KT + 32), "r"(m0), "r"(sb + SMEM_FULL(jj)) : "memory");
            asm volatile(
                "cp.async.bulk.tensor.2d.shared::cta.global.tile.mbarrier::complete_tx::bytes "
                "[%0], [%1, {%2, %3}], [%4];"
                :: "r"(sb + SMEM_B(jj)), "l"(&tma_b),
                   "r"(0), "r"(j * OUT_DIM), "r"(sb + SMEM_FULL(jj)) : "memory");
        }
    }

    // ---- per-thread ldmatrix addressing (SW128 swizzle, conflict-free) ----
    const int laneq = lane >> 2;                 // 0..7
    const int laner = lane & 3;                  // 0..3
    const uint32_t l7 = lane & 7;
    const uint32_t xorv = l7 << 4;               // SW128: off ^= (row&7)<<4

    // A (fp32, rows=token 128B): x4 tiles {rows+0,c},{rows+8,c},{rows+0,c+16B},{rows+8,c+16B}
    const uint32_t aRowSel = ((lane >> 3) & 1) << 3;
    const uint32_t aColSel = (uint32_t)(lane >> 4) << 4;
    const uint32_t aBase = (uint32_t)(warp_m * 64 + aRowSel + l7) * 128;

    // B (fp16 slot-permuted, rows=n 128B): x4 tiles {n rows, c},{n rows, c+16B},{n+8, c},{n+8, c+16B}
    const uint32_t bRowSel = (uint32_t)(lane >> 4) << 3;
    const uint32_t bColSel = ((lane >> 3) & 1) << 4;
    const uint32_t bBase = (uint32_t)(warp_n * 64 + bRowSel + l7) * 128;

    float c[4][8][4];
    #pragma unroll
    for (int mi = 0; mi < 4; mi++)
        #pragma unroll
        for (int ni = 0; ni < 8; ni++)
            #pragma unroll
            for (int r = 0; r < 4; r++) c[mi][ni][r] = 0.0f;

    int slot = 0, ph = 0;
    for (int s = 0; s < nstage; ++s) {
        MBARRIER_WAIT_PARITY(sb + SMEM_FULL(slot), ph);

        const uint32_t As = sb + SMEM_A(slot);
        const uint32_t Bs = sb + SMEM_B(slot);

        #pragma unroll
        for (int t = 0; t < 4; t++) {            // 4 x (K=16) per stage
            const uint32_t Asub = As + ((uint32_t)(t >> 1) * 16384);
            const uint32_t kbA = (uint32_t)(t & 1) * 64;      // byte base within sub-tile row
            const uint32_t aOffLo = (kbA + aColSel) ^ xorv;        // phys k 0-7
            const uint32_t aOffHi = (kbA + 32 + aColSel) ^ xorv;   // phys k 8-15
            const uint32_t bOff = ((uint32_t)t * 32 + bColSel) ^ xorv;

            // A fragments: 2x ldmatrix.x4 per m-tile, pack to fp16x2 in slot order
            uint32_t a[4][4];
            #pragma unroll
            for (int mi = 0; mi < 4; mi++) {
                uint32_t q0, q1, q2, q3, p0, p1, p2, p3;
                LDSM_X4(q0, q1, q2, q3, Asub + aBase + (uint32_t)mi * 2048 + aOffLo);
                LDSM_X4(p0, p1, p2, p3, Asub + aBase + (uint32_t)mi * 2048 + aOffHi);
                a[mi][0] = pack_f16x2(q2, q0);   // slots (2r, 2r+1) = phys (r, r+4)
                a[mi][1] = pack_f16x2(q3, q1);
                a[mi][2] = pack_f16x2(p2, p0);   // slots (2r+8, 2r+9) = phys (8+r, 12+r)
                a[mi][3] = pack_f16x2(p3, p1);
            }

            // B fragments: 4x ldmatrix.x4 (2 ni each, K=16), MMA as they land
            #pragma unroll
            for (int ni2 = 0; ni2 < 4; ni2++) {
                uint32_t b0, b1, b2, b3;   // b0/b1 -> ni=2*ni2, b2/b3 -> ni=2*ni2+1
                LDSM_X4(b0, b1, b2, b3, Bs + bBase + (uint32_t)ni2 * 2048 + bOff);
                #pragma unroll
                for (int mi = 0; mi < 4; mi++)
                    mma_f16(c[mi][2 * ni2], a[mi][0], a[mi][1], a[mi][2], a[mi][3], b0, b1);
                #pragma unroll
                for (int mi = 0; mi < 4; mi++)
                    mma_f16(c[mi][2 * ni2 + 1], a[mi][0], a[mi][1], a[mi][2], a[mi][3], b2, b3);
            }
        }

        __syncwarp();
        if (lane == 0) MBARRIER_ARRIVE(sb + SMEM_EMPTY(slot));

        // producer: refill this slot for stage s+3 once all 8 warps drained it
        if (tid == 0 && s + STAGES < nstage) {
            MBARRIER_WAIT_PARITY(sb + SMEM_EMPTY(slot), ph);
            const int j = s0 + s + STAGES;
            MBARRIER_EXPECT_TX(sb + SMEM_FULL(slot), STAGE_TX);
            asm volatile(
                "cp.async.bulk.tensor.2d.shared::cta.global.tile.mbarrier::complete_tx::bytes "
                "[%0], [%1, {%2, %3}], [%4];"
                :: "r"(sb + SMEM_A(slot)), "l"(&tma_a),
                   "r"(j * KT), "r"(m0), "r"(sb + SMEM_FULL(slot)) : "memory");
            asm volatile(
                "cp.async.bulk.tensor.2d.shared::cta.global.tile.mbarrier::complete_tx::bytes "
                "[%0], [%1, {%2, %3}], [%4];"
                :: "r"(sb + SMEM_A(slot) + 16384), "l"(&tma_a),
                   "r"(j * KT + 32), "r"(m0), "r"(sb + SMEM_FULL(slot)) : "memory");
            asm volatile(
                "cp.async.bulk.tensor.2d.shared::cta.global.tile.mbarrier::complete_tx::bytes "
                "[%0], [%1, {%2, %3}], [%4];"
                :: "r"(sb + SMEM_B(slot)), "l"(&tma_b),
                   "r"(0), "r"(j * OUT_DIM), "r"(sb + SMEM_FULL(slot)) : "memory");
        }

        if (++slot == STAGES) { slot = 0; ph ^= 1; }
    }

    // epilogue: frag c0,c1 @ (row=laneq, col=laner*2), c2,c3 @ row+8
    #pragma unroll
    for (int mi = 0; mi < 4; mi++) {
        const int row = warp_m * 64 + mi * 16 + laneq;
        #pragma unroll
        for (int ni = 0; ni < 8; ni++) {
            const int col = warp_n * 64 + ni * 8 + laner * 2;
            float2* p0 = reinterpret_cast<float2*>(obase + (size_t)row * OUT_DIM + col);
            float2* p1 = reinterpret_cast<float2*>(obase + (size_t)(row + 8) * OUT_DIM + col);
            *p0 = make_float2(c[mi][ni][0], c[mi][ni][1]);
            *p1 = make_float2(c[mi][ni][2], c[mi][ni][3]);
        }
    }

    // ---- in-kernel split-K reduction: last quarter-CTA of each tile sums partials ----
    // (flag lives in dynamic smem @512 so no static __shared__ shifts the smem base;
    //  out may be only 8B-aligned -> float2 stores only)
    if (qt >= 0) {
        volatile int* s_last = reinterpret_cast<volatile int*>(smem + SMEM_LAST);
        __threadfence();                       // release partial stores
        if (tid == 0) {
            int old = atomicAdd(&g_cnt[qt], 1);
            *s_last = (old == 3);
            if (old == 3) g_cnt[qt] = 0;       // self-reset for next launch / graph replay
        }
        __syncthreads();
        if (*s_last) {
            __threadfence();                   // acquire other quarters' stores
            const float2* p = reinterpret_cast<const float2*>(g_part + (size_t)(qt * 4) * TILE_ELEMS);
            float2* o = reinterpret_cast<float2*>(out + (size_t)m_tile * TILE_ELEMS);
            const int n2 = TILE_ELEMS / 2;     // 16384 float2s
            for (int i = tid; i < n2; i += 256) {
                float2 v0 = p[i];
                float2 v1 = p[i + n2];
                float2 v2 = p[i + 2 * n2];
                float2 v3 = p[i + 3 * n2];
                o[i] = make_float2(v0.x + v1.x + v2.x + v3.x,
                                   v0.y + v1.y + v2.y + v3.y);
            }
        }
    }
}

// ---------------- Host launch ----------------
typedef CUresult (*cuTensorMapEncodeTiled_t)(
    CUtensorMap*, CUtensorMapDataType, cuuint32_t, void*,
    const cuuint64_t*, const cuuint64_t*, const cuuint32_t*, const cuuint32_t*,
    CUtensorMapInterleave, CUtensorMapSwizzle, CUtensorMapL2promotion, CUtensorMapFloatOOBfill);

extern "C" void kernel_launch(void* const* d_in, const int* in_sizes, int n_in,
                              void* d_out, int out_size) {
    const float* x = (const float*)d_in[0];
    const float* w = (const float*)d_in[1];
    float* out = (float*)d_out;

    __half* wt_ptr = nullptr;
    cudaGetSymbolAddress((void**)&wt_ptr, g_wt);

    // 1) tanh(W) -> fp16, K-slot-permuted scratch
    int nw = OUT_DIM * IN_DIM;
    tanh_prep_kernel<<<(nw + 255) / 256, 256>>>(w, wt_ptr);

    // 2) tensormaps via driver entry point
    cuTensorMapEncodeTiled_t encode = nullptr;
    cudaDriverEntryPointQueryResult qres;
    cudaGetDriverEntryPoint("cuTensorMapEncodeTiled", (void**)&encode,
                            cudaEnableDefault, &qres);

    CUtensorMap tma_a, tma_b;
    {
        cuuint64_t dims[2]    = {IN_DIM, TOKENS};
        cuuint64_t strides[1] = {(cuuint64_t)IN_DIM * 4};
        cuuint32_t box[2]     = {32, TILE_M};          // 32 fp32 = 128B rows (SW128 atom)
        cuuint32_t estr[2]    = {1, 1};
        encode(&tma_a, CU_TENSOR_MAP_DATA_TYPE_FLOAT32, 2, (void*)x,
               dims, strides, box, estr,
               CU_TENSOR_MAP_INTERLEAVE_NONE, CU_TENSOR_MAP_SWIZZLE_128B,
               CU_TENSOR_MAP_L2_PROMOTION_L2_128B, CU_TENSOR_MAP_FLOAT_OOB_FILL_NONE);
    }
    {
        // wt layout: [IN_DIM/64][OUT_DIM][64 fp16]; row = 64 fp16 = 128 bytes
        cuuint64_t dims[2]    = {KT, (cuuint64_t)OUT_DIM * (IN_DIM / KT)};
        cuuint64_t strides[1] = {(cuuint64_t)KT * 2};
        cuuint32_t box[2]     = {KT, OUT_DIM};         // 64 fp16 = 128B rows
        cuuint32_t estr[2]    = {1, 1};
        encode(&tma_b, CU_TENSOR_MAP_DATA_TYPE_FLOAT16, 2, (void*)wt_ptr,
               dims, strides, box, estr,
               CU_TENSOR_MAP_INTERLEAVE_NONE, CU_TENSOR_MAP_SWIZZLE_128B,
               CU_TENSOR_MAP_L2_PROMOTION_L2_128B, CU_TENSOR_MAP_FLOAT_OOB_FILL_NONE);
    }

    // 3) GEMM: 148 full-K CTAs first (long jobs), then 432 quarter-K CTAs (tail
    //    fill); last quarter-CTA per tile reduces partials in-kernel.
    cudaFuncSetAttribute(gemm_f16_kernel, cudaFuncAttributeMaxDynamicSharedMemorySize, SMEM_TOTAL);
    gemm_f16_kernel<<<N_FULL + 4 * N_QTILE, 256, SMEM_TOTAL>>>(tma_a, tma_b, out);
}

// round 17
// speedup vs baseline: 1.1177x; 1.1177x over previous
#include <cuda_runtime.h>
#include <cuda.h>
#include <cuda_fp16.h>
#include <cstdint>

// Problem dims
#define TOKENS  32768
#define IN_DIM  8192
#define OUT_DIM 256

// Tiling
#define TILE_M 128
#define KT 64                       // K elements per pipeline stage
#define STAGES 3
#define NS (IN_DIM / KT)            // 128 K-stages (full-K CTA)

// LPT split-K schedule: 148 full-K CTAs + 108 tiles x 4 quarter-K CTAs
#define N_FULL  148
#define N_QTILE (TOKENS / TILE_M - N_FULL)   // 108
#define QSTAGES (NS / 4)                      // 32
#define TILE_ELEMS (TILE_M * OUT_DIM)         // 32768

#define A_STAGE_BYTES (TILE_M * KT * 4)    // 32768 (two 16KB TMA boxes)
#define B_STAGE_BYTES (OUT_DIM * KT * 2)   // 32768 (fp16, slot-permuted)
#define STAGE_TX      (A_STAGE_BYTES + B_STAGE_BYTES)   // 65536

// SMEM layout (all inside the dynamic region; NO static __shared__ anywhere —
// a static would shift the extern smem base and break mbarrier 8B alignment)
#define SMEM_FULL(s)  ((s) * 16)
#define SMEM_EMPTY(s) ((s) * 16 + 8)
#define SMEM_A(s)     (1024 + (s) * A_STAGE_BYTES)
#define SMEM_B(s)     (1024 + STAGES * A_STAGE_BYTES + (s) * B_STAGE_BYTES)
#define SMEM_TOTAL    (1024 + STAGES * (A_STAGE_BYTES + B_STAGE_BYTES))   // 197632

// tanh(W) as fp16, K-permuted into MMA slot order, 4 MB device scratch.
__device__ __align__(16) __half g_wt[OUT_DIM * IN_DIM];
// fp32 partials for quarter-K CTAs: [qtile][quarter][128*256]  (56.6 MB)
__device__ __align__(16) float g_part[N_QTILE * 4 * TILE_ELEMS];

// ---------------- PTX helpers ----------------
__device__ __forceinline__ uint32_t smem_u32(const void* p) {
    uint32_t a;
    asm("{ .reg .u64 t; cvta.to.shared.u64 t, %1; cvt.u32.u64 %0, t; }" : "=r"(a) : "l"(p));
    return a;
}

#define MBARRIER_INIT(addr, cnt) \
    asm volatile("mbarrier.init.shared.b64 [%0], %1;" :: "r"((uint32_t)(addr)), "r"((uint32_t)(cnt)) : "memory")

#define MBARRIER_ARRIVE(addr) \
    asm volatile("mbarrier.arrive.shared.b64 _, [%0];" :: "r"((uint32_t)(addr)) : "memory")

#define MBARRIER_EXPECT_TX(addr, bytes) \
    asm volatile("mbarrier.arrive.expect_tx.shared.b64 _, [%0], %1;" :: "r"((uint32_t)(addr)), "r"((uint32_t)(bytes)) : "memory")

#define MBARRIER_WAIT_PARITY(mbar_smem_addr, phase_parity) do { \
    uint32_t _mbar = (uint32_t)(mbar_smem_addr); \
    uint32_t _parity = (uint32_t)(phase_parity); \
    uint32_t _done; \
    asm volatile( \
        "{\n\t" \
        ".reg .pred p;\n\t" \
        "mbarrier.try_wait.parity.acquire.cta.shared::cta.b64 p, [%1], %2;\n\t" \
        "selp.b32 %0, 1, 0, p;\n\t" \
        "}" \
        : "=r"(_done) : "r"(_mbar), "r"(_parity) : "memory"); \
    if (!_done) { \
        asm volatile( \
            "{\n\t" \
            ".reg .pred P1;\n\t" \
            "WAIT_LOOP_%=:\n\t" \
            "mbarrier.try_wait.parity.acquire.cta.shared::cta.b64 P1, [%0], %1, 0x989680;\n\t" \
            "@P1 bra.uni WAIT_DONE_%=;\n\t" \
            "bra.uni WAIT_LOOP_%=;\n\t" \
            "WAIT_DONE_%=:\n\t" \
            "}" \
            :: "r"(_mbar), "r"(_parity) : "memory"); \
    } \
} while(0)

#define LDSM_X4(r0, r1, r2, r3, addr) \
    asm volatile("ldmatrix.sync.aligned.m8n8.x4.shared.b16 {%0,%1,%2,%3}, [%4];" \
        : "=r"(r0), "=r"(r1), "=r"(r2), "=r"(r3) : "r"(addr))

// pack two fp32 (given as raw bits) into fp16x2: hi half <- h, lo half <- l
__device__ __forceinline__ uint32_t pack_f16x2(uint32_t h, uint32_t l) {
    uint32_t d;
    asm("cvt.rn.f16x2.f32 %0, %1, %2;" : "=r"(d) : "f"(__uint_as_float(h)), "f"(__uint_as_float(l)));
    return d;
}

__device__ __forceinline__ void mma_f16(float c[4], uint32_t a0, uint32_t a1, uint32_t a2, uint32_t a3,
                                        uint32_t b0, uint32_t b1) {
    asm volatile(
        "mma.sync.aligned.m16n8k16.row.col.f32.f16.f16.f32 "
        "{%0,%1,%2,%3}, {%4,%5,%6,%7}, {%8,%9}, {%0,%1,%2,%3};"
        : "+f"(c[0]), "+f"(c[1]), "+f"(c[2]), "+f"(c[3])
        : "r"(a0), "r"(a1), "r"(a2), "r"(a3), "r"(b0), "r"(b1));
}

// ---------------- Kernels ----------------

// tanh(W) -> fp16 (hardware tanh.approx: MUFU, ~2^-11 rel err, below fp16
// quantization), written K-permuted into MMA-slot order.
// For phys k position p (0..15) within a 16-chunk:
//   slot = 2*(p&3) + ((p>>2)&1) + (p&8)
__global__ void tanh_prep_kernel(const float* __restrict__ w, __half* __restrict__ wt) {
    int i = blockIdx.x * blockDim.x + threadIdx.x;
    if (i < OUT_DIM * IN_DIM) {
        int n = i / IN_DIM, k = i % IN_DIM;
        int kc = k >> 6, j = k & 63, c = (j >> 4) & 3, p = j & 15;
        int slot = ((p & 3) << 1) + ((p >> 2) & 1) + (p & 8);
        int dst = ((kc * OUT_DIM + n) << 6) + (c << 4) + slot;
        float t;
        asm("tanh.approx.f32 %0, %1;" : "=f"(t) : "f"(w[i]));
        wt[dst] = __float2half_rn(t);
    }
}

// sum 4 quarter-K partials per split tile into out (full-chip spread)
__global__ void reduce_part_kernel(float* __restrict__ out) {
    int i = blockIdx.x * blockDim.x + threadIdx.x;
    if (i < N_QTILE * TILE_ELEMS) {
        int qt = i / TILE_ELEMS;
        int rem = i - qt * TILE_ELEMS;
        const float* p = g_part + (size_t)(qt * 4) * TILE_ELEMS + rem;
        float v = p[0] + p[TILE_ELEMS] + p[2 * TILE_ELEMS] + p[3 * TILE_ELEMS];
        out[(size_t)(N_FULL + qt) * TILE_ELEMS + rem] = v;
    }
}

__global__ void __launch_bounds__(256, 1) gemm_f16_kernel(
    const __grid_constant__ CUtensorMap tma_a,
    const __grid_constant__ CUtensorMap tma_b,
    float* __restrict__ out)
{
    extern __shared__ char smem[];
    uint32_t sb = smem_u32(smem);
    const int tid = threadIdx.x;
    const int wid = tid >> 5;
    const int lane = tid & 31;
    const int warp_m = wid & 1;        // 2-way M split (64 rows each)
    const int warp_n = wid >> 1;       // 4-way N split (64 cols each)

    // ---- work decode: full-K tile or quarter-K slice ----
    const int bid = blockIdx.x;
    int m_tile, s0, nstage;
    float* obase;
    if (bid < N_FULL) {
        m_tile = bid; s0 = 0; nstage = NS;
        obase = out + (size_t)m_tile * TILE_ELEMS;
    } else {
        const int q = bid - N_FULL;
        m_tile = N_FULL + (q >> 2);
        s0 = (q & 3) * QSTAGES; nstage = QSTAGES;
        obase = g_part + (size_t)q * TILE_ELEMS;
    }
    const int m0 = m_tile * TILE_M;

    if (tid == 0) {
        #pragma unroll
        for (int s = 0; s < STAGES; s++) {
            MBARRIER_INIT(sb + SMEM_FULL(s), 1);
            MBARRIER_INIT(sb + SMEM_EMPTY(s), 8);   // one arrive per warp
        }
    }
    __syncthreads();

    // prologue: fill all 3 stages
    if (tid == 0) {
        #pragma unroll
        for (int jj = 0; jj < STAGES; jj++) {
            const int j = s0 + jj;
            MBARRIER_EXPECT_TX(sb + SMEM_FULL(jj), STAGE_TX);
            asm volatile(
                "cp.async.bulk.tensor.2d.shared::cta.global.tile.mbarrier::complete_tx::bytes "
                "[%0], [%1, {%2, %3}], [%4];"
                :: "r"(sb + SMEM_A(jj)), "l"(&tma_a),
                   "r"(j * KT), "r"(m0), "r"(sb + SMEM_FULL(jj)) : "memory");
            asm volatile(
                "cp.async.bulk.tensor.2d.shared::cta.global.tile.mbarrier::complete_tx::bytes "
                "[%0], [%1, {%2, %3}], [%4];"
                :: "r"(sb + SMEM_A(jj) + 16384), "l"(&tma_a),
                   "r"(j * KT + 32), "r"(m0), "r"(sb + SMEM_FULL(jj)) : "memory");
            asm volatile(
                "cp.async.bulk.tensor.2d.shared::cta.global.tile.mbarrier::complete_tx::bytes "
                "[%0], [%1, {%2, %3}], [%4];"
                :: "r"(sb + SMEM_B(jj)), "l"(&tma_b),
                   "r"(0), "r"(j * OUT_DIM), "r"(sb + SMEM_FULL(jj)) : "memory");
        }
    }

    // ---- per-thread ldmatrix addressing (SW128 swizzle, conflict-free) ----
    const int laneq = lane >> 2;                 // 0..7
    const int laner = lane & 3;                  // 0..3
    const uint32_t l7 = lane & 7;
    const uint32_t xorv = l7 << 4;               // SW128: off ^= (row&7)<<4

    // A (fp32, rows=token 128B): x4 tiles {rows+0,c},{rows+8,c},{rows+0,c+16B},{rows+8,c+16B}
    const uint32_t aRowSel = ((lane >> 3) & 1) << 3;
    const uint32_t aColSel = (uint32_t)(lane >> 4) << 4;
    const uint32_t aBase = (uint32_t)(warp_m * 64 + aRowSel + l7) * 128;

    // B (fp16 slot-permuted, rows=n 128B): x4 tiles {n rows, c},{n rows, c+16B},{n+8, c},{n+8, c+16B}
    const uint32_t bRowSel = (uint32_t)(lane >> 4) << 3;
    const uint32_t bColSel = ((lane >> 3) & 1) << 4;
    const uint32_t bBase = (uint32_t)(warp_n * 64 + bRowSel + l7) * 128;

    float c[4][8][4];
    #pragma unroll
    for (int mi = 0; mi < 4; mi++)
        #pragma unroll
        for (int ni = 0; ni < 8; ni++)
            #pragma unroll
            for (int r = 0; r < 4; r++) c[mi][ni][r] = 0.0f;

    int slot = 0, ph = 0;
    for (int s = 0; s < nstage; ++s) {
        MBARRIER_WAIT_PARITY(sb + SMEM_FULL(slot), ph);

        const uint32_t As = sb + SMEM_A(slot);
        const uint32_t Bs = sb + SMEM_B(slot);

        #pragma unroll
        for (int t = 0; t < 4; t++) {            // 4 x (K=16) per stage
            const uint32_t Asub = As + ((uint32_t)(t >> 1) * 16384);
            const uint32_t kbA = (uint32_t)(t & 1) * 64;      // byte base within sub-tile row
            const uint32_t aOffLo = (kbA + aColSel) ^ xorv;        // phys k 0-7
            const uint32_t aOffHi = (kbA + 32 + aColSel) ^ xorv;   // phys k 8-15
            const uint32_t bOff = ((uint32_t)t * 32 + bColSel) ^ xorv;

            // A fragments: 2x ldmatrix.x4 per m-tile, pack to fp16x2 in slot order
            uint32_t a[4][4];
            #pragma unroll
            for (int mi = 0; mi < 4; mi++) {
                uint32_t q0, q1, q2, q3, p0, p1, p2, p3;
                LDSM_X4(q0, q1, q2, q3, Asub + aBase + (uint32_t)mi * 2048 + aOffLo);
                LDSM_X4(p0, p1, p2, p3, Asub + aBase + (uint32_t)mi * 2048 + aOffHi);
                a[mi][0] = pack_f16x2(q2, q0);   // slots (2r, 2r+1) = phys (r, r+4)
                a[mi][1] = pack_f16x2(q3, q1);
                a[mi][2] = pack_f16x2(p2, p0);   // slots (2r+8, 2r+9) = phys (8+r, 12+r)
                a[mi][3] = pack_f16x2(p3, p1);
            }

            // B fragments: 4x ldmatrix.x4 (2 ni each, K=16), MMA as they land
            #pragma unroll
            for (int ni2 = 0; ni2 < 4; ni2++) {
                uint32_t b0, b1, b2, b3;   // b0/b1 -> ni=2*ni2, b2/b3 -> ni=2*ni2+1
                LDSM_X4(b0, b1, b2, b3, Bs + bBase + (uint32_t)ni2 * 2048 + bOff);
                #pragma unroll
                for (int mi = 0; mi < 4; mi++)
                    mma_f16(c[mi][2 * ni2], a[mi][0], a[mi][1], a[mi][2], a[mi][3], b0, b1);
                #pragma unroll
                for (int mi = 0; mi < 4; mi++)
                    mma_f16(c[mi][2 * ni2 + 1], a[mi][0], a[mi][1], a[mi][2], a[mi][3], b2, b3);
            }
        }

        __syncwarp();
        if (lane == 0) MBARRIER_ARRIVE(sb + SMEM_EMPTY(slot));

        // producer: refill this slot for stage s+3 once all 8 warps drained it
        if (tid == 0 && s + STAGES < nstage) {
            MBARRIER_WAIT_PARITY(sb + SMEM_EMPTY(slot), ph);
            const int j = s0 + s + STAGES;
            MBARRIER_EXPECT_TX(sb + SMEM_FULL(slot), STAGE_TX);
            asm volatile(
                "cp.async.bulk.tensor.2d.shared::cta.global.tile.mbarrier::complete_tx::bytes "
                "[%0], [%1, {%2, %3}], [%4];"
                :: "r"(sb + SMEM_A(slot)), "l"(&tma_a),
                   "r"(j * KT), "r"(m0), "r"(sb + SMEM_FULL(slot)) : "memory");
            asm volatile(
                "cp.async.bulk.tensor.2d.shared::cta.global.tile.mbarrier::complete_tx::bytes "
                "[%0], [%1, {%2, %3}], [%4];"
                :: "r"(sb + SMEM_A(slot) + 16384), "l"(&tma_a),
                   "r"(j * KT + 32), "r"(m0), "r"(sb + SMEM_FULL(slot)) : "memory");
            asm volatile(
                "cp.async.bulk.tensor.2d.shared::cta.global.tile.mbarrier::complete_tx::bytes "
                "[%0], [%1, {%2, %3}], [%4];"
                :: "r"(sb + SMEM_B(slot)), "l"(&tma_b),
                   "r"(0), "r"(j * OUT_DIM), "r"(sb + SMEM_FULL(slot)) : "memory");
        }

        if (++slot == STAGES) { slot = 0; ph ^= 1; }
    }

    // epilogue: frag c0,c1 @ (row=laneq, col=laner*2), c2,c3 @ row+8
    #pragma unroll
    for (int mi = 0; mi < 4; mi++) {
        const int row = warp_m * 64 + mi * 16 + laneq;
        #pragma unroll
        for (int ni = 0; ni < 8; ni++) {
            const int col = warp_n * 64 + ni * 8 + laner * 2;
            float2* p0 = reinterpret_cast<float2*>(obase + (size_t)row * OUT_DIM + col);
            float2* p1 = reinterpret_cast<float2*>(obase + (size_t)(row + 8) * OUT_DIM + col);
            *p0 = make_float2(c[mi][ni][0], c[mi][ni][1]);
            *p1 = make_float2(c[mi][ni][2], c[mi][ni][3]);
        }
    }
}

// ---------------- Host launch ----------------
typedef CUresult (*cuTensorMapEncodeTiled_t)(
    CUtensorMap*, CUtensorMapDataType, cuuint32_t, void*,
    const cuuint64_t*, const cuuint64_t*, const cuuint32_t*, const cuuint32_t*,
    CUtensorMapInterleave, CUtensorMapSwizzle, CUtensorMapL2promotion, CUtensorMapFloatOOBfill);

extern "C" void kernel_launch(void* const* d_in, const int* in_sizes, int n_in,
                              void* d_out, int out_size) {
    const float* x = (const float*)d_in[0];
    const float* w = (const float*)d_in[1];
    float* out = (float*)d_out;

    __half* wt_ptr = nullptr;
    cudaGetSymbolAddress((void**)&wt_ptr, g_wt);

    // 1) tanh(W) -> fp16, K-slot-permuted scratch
    int nw = OUT_DIM * IN_DIM;
    tanh_prep_kernel<<<(nw + 255) / 256, 256>>>(w, wt_ptr);

    // 2) tensormaps via driver entry point
    cuTensorMapEncodeTiled_t encode = nullptr;
    cudaDriverEntryPointQueryResult qres;
    cudaGetDriverEntryPoint("cuTensorMapEncodeTiled", (void**)&encode,
                            cudaEnableDefault, &qres);

    CUtensorMap tma_a, tma_b;
    {
        cuuint64_t dims[2]    = {IN_DIM, TOKENS};
        cuuint64_t strides[1] = {(cuuint64_t)IN_DIM * 4};
        cuuint32_t box[2]     = {32, TILE_M};          // 32 fp32 = 128B rows (SW128 atom)
        cuuint32_t estr[2]    = {1, 1};
        encode(&tma_a, CU_TENSOR_MAP_DATA_TYPE_FLOAT32, 2, (void*)x,
               dims, strides, box, estr,
               CU_TENSOR_MAP_INTERLEAVE_NONE, CU_TENSOR_MAP_SWIZZLE_128B,
               CU_TENSOR_MAP_L2_PROMOTION_L2_128B, CU_TENSOR_MAP_FLOAT_OOB_FILL_NONE);
    }
    {
        // wt layout: [IN_DIM/64][OUT_DIM][64 fp16]; row = 64 fp16 = 128 bytes
        cuuint64_t dims[2]    = {KT, (cuuint64_t)OUT_DIM * (IN_DIM / KT)};
        cuuint64_t strides[1] = {(cuuint64_t)KT * 2};
        cuuint32_t box[2]     = {KT, OUT_DIM};         // 64 fp16 = 128B rows
        cuuint32_t estr[2]    = {1, 1};
        encode(&tma_b, CU_TENSOR_MAP_DATA_TYPE_FLOAT16, 2, (void*)wt_ptr,
               dims, strides, box, estr,
               CU_TENSOR_MAP_INTERLEAVE_NONE, CU_TENSOR_MAP_SWIZZLE_128B,
               CU_TENSOR_MAP_L2_PROMOTION_L2_128B, CU_TENSOR_MAP_FLOAT_OOB_FILL_NONE);
    }

    // 3) GEMM: 148 full-K CTAs first (long jobs), then 432 quarter-K CTAs (tail fill)
    cudaFuncSetAttribute(gemm_f16_kernel, cudaFuncAttributeMaxDynamicSharedMemorySize, SMEM_TOTAL);
    gemm_f16_kernel<<<N_FULL + 4 * N_QTILE, 256, SMEM_TOTAL>>>(tma_a, tma_b, out);

    // 4) reduce quarter-K partials into out for the 108 split tiles (full-chip spread)
    int nred = N_QTILE * TILE_ELEMS;
    reduce_part_kernel<<<(nred + 255) / 256, 256>>>(out);
}